// round 1
// baseline (speedup 1.0000x reference)
#include <cuda_runtime.h>
#include <cuda_bf16.h>
#include <cstdint>

#define BATCH 2
#define NANCH 261888
#define PRE_NMS 6000
#define PROP 1000
#define NMS_THR 0.7f
#define NBINS 4096
#define CAP 16384
#define NWORDS 94   // ceil(6000/64)

// ---------------- scratch (static device globals; no allocation) ----------------
__device__ int g_hist[BATCH * NBINS];
__device__ int g_counts[BATCH];
__device__ int g_cutbin[BATCH];
__device__ unsigned long long g_cand[BATCH * CAP];
__device__ int g_topidx[BATCH * PRE_NMS];
__device__ float4 g_boxes[BATCH * PRE_NMS];
__device__ unsigned long long g_mask[(size_t)BATCH * PRE_NMS * NWORDS]; // ~9MB

// ---------------- kernels ----------------

__global__ void zero_kernel() {
    int t = blockIdx.x * blockDim.x + threadIdx.x;
    if (t < BATCH * NBINS) g_hist[t] = 0;
    if (t < BATCH) g_counts[t] = 0;
}

__device__ __forceinline__ int score_bin(float s) {
    int b = (int)(s * (float)NBINS);
    if (b < 0) b = 0;
    if (b > NBINS - 1) b = NBINS - 1;
    return b;
}

__global__ void hist_kernel(const float2* __restrict__ cls) {
    __shared__ int h[BATCH * NBINS];
    for (int t = threadIdx.x; t < BATCH * NBINS; t += blockDim.x) h[t] = 0;
    __syncthreads();
    const long long total = (long long)BATCH * NANCH;
    for (long long t = blockIdx.x * (long long)blockDim.x + threadIdx.x; t < total;
         t += (long long)gridDim.x * blockDim.x) {
        int b = (int)(t / NANCH);
        float s = cls[t].y;           // rpn_class[...,1]
        atomicAdd(&h[b * NBINS + score_bin(s)], 1);
    }
    __syncthreads();
    for (int t = threadIdx.x; t < BATCH * NBINS; t += blockDim.x)
        if (h[t]) atomicAdd(&g_hist[t], h[t]);
}

__global__ void cutbin_kernel() {
    int b = blockIdx.x;
    __shared__ int h[NBINS];
    for (int t = threadIdx.x; t < NBINS; t += blockDim.x) h[t] = g_hist[b * NBINS + t];
    __syncthreads();
    if (threadIdx.x == 0) {
        int acc = 0, c = 0;
        for (int bin = NBINS - 1; bin >= 0; --bin) {
            acc += h[bin];
            if (acc >= PRE_NMS) { c = bin; break; }
        }
        g_cutbin[b] = c;
    }
}

__global__ void compact_kernel(const float2* __restrict__ cls) {
    long long t = blockIdx.x * (long long)blockDim.x + threadIdx.x;
    const long long total = (long long)BATCH * NANCH;
    if (t >= total) return;
    int b = (int)(t / NANCH);
    int i = (int)(t - (long long)b * NANCH);
    float s = cls[t].y;
    if (score_bin(s) >= g_cutbin[b]) {
        int p = atomicAdd(&g_counts[b], 1);
        if (p < CAP) {
            unsigned int sb = __float_as_uint(s); // s in [0,1): positive -> bit-monotonic
            g_cand[b * CAP + p] =
                ((unsigned long long)sb << 32) | (unsigned long long)(0xFFFFFFFFu - (unsigned)i);
        }
    }
}

// single-block bitonic sort (descending) of up to CAP 64-bit keys; emit top-6000 indices
__global__ void sort_kernel() {
    extern __shared__ unsigned long long skey[];
    int b = blockIdx.x;
    int cnt = g_counts[b];
    if (cnt > CAP) cnt = CAP;
    for (int t = threadIdx.x; t < CAP; t += blockDim.x)
        skey[t] = (t < cnt) ? g_cand[b * CAP + t] : 0ULL;
    __syncthreads();
    for (int k = 2; k <= CAP; k <<= 1) {
        for (int j = k >> 1; j > 0; j >>= 1) {
            for (int i = threadIdx.x; i < CAP; i += blockDim.x) {
                int ixj = i ^ j;
                if (ixj > i) {
                    bool dir = ((i & k) == 0); // dir=true -> descending segment
                    unsigned long long a = skey[i], c = skey[ixj];
                    if ((a < c) == dir) { skey[i] = c; skey[ixj] = a; }
                }
            }
            __syncthreads();
        }
    }
    for (int t = threadIdx.x; t < PRE_NMS; t += blockDim.x) {
        unsigned int low = (unsigned int)(skey[t] & 0xFFFFFFFFu);
        g_topidx[b * PRE_NMS + t] = (int)(0xFFFFFFFFu - low);
    }
}

__global__ void boxes_kernel(const float* __restrict__ rpn_bbox,
                             const float* __restrict__ anchors) {
    int t = blockIdx.x * blockDim.x + threadIdx.x;
    if (t >= BATCH * PRE_NMS) return;
    int b = t / PRE_NMS;
    int idx = g_topidx[t];
    size_t base = ((size_t)b * NANCH + (size_t)idx) * 4;
    float a0 = anchors[base + 0], a1 = anchors[base + 1];
    float a2 = anchors[base + 2], a3 = anchors[base + 3];
    float d0 = rpn_bbox[base + 0] * 0.1f;
    float d1 = rpn_bbox[base + 1] * 0.1f;
    float d2 = rpn_bbox[base + 2] * 0.2f;
    float d3 = rpn_bbox[base + 3] * 0.2f;
    float h = a2 - a0, w = a3 - a1;
    float cy = a0 + 0.5f * h + d0 * h;
    float cx = a1 + 0.5f * w + d1 * w;
    h = h * expf(d2);
    w = w * expf(d3);
    float y1 = cy - 0.5f * h;
    float x1 = cx - 0.5f * w;
    float y2 = y1 + h;
    float x2 = x1 + w;
    y1 = fminf(fmaxf(y1, 0.f), 1.f);
    x1 = fminf(fmaxf(x1, 0.f), 1.f);
    y2 = fminf(fmaxf(y2, 0.f), 1.f);
    x2 = fminf(fmaxf(x2, 0.f), 1.f);
    g_boxes[t] = make_float4(y1, x1, y2, x2);
}

// 64x64 tile IoU>thr bitmask (torchvision style)
__global__ void mask_kernel() {
    int b = blockIdx.z;
    int row0 = blockIdx.y * 64;
    int col0 = blockIdx.x * 64;
    __shared__ float4 cbox[64];
    int t = threadIdx.x;
    int c = col0 + t;
    cbox[t] = (c < PRE_NMS) ? g_boxes[b * PRE_NMS + c] : make_float4(0.f, 0.f, 0.f, 0.f);
    __syncthreads();
    int r = row0 + t;
    if (r >= PRE_NMS) return;
    float4 rb = g_boxes[b * PRE_NMS + r];
    float areaR = (rb.z - rb.x) * (rb.w - rb.y);
    unsigned long long bits = 0ULL;
#pragma unroll 8
    for (int jj = 0; jj < 64; ++jj) {
        float4 cb = cbox[jj];
        float areaC = (cb.z - cb.x) * (cb.w - cb.y);
        float ih = fmaxf(fminf(rb.z, cb.z) - fmaxf(rb.x, cb.x), 0.f);
        float iw = fmaxf(fminf(rb.w, cb.w) - fmaxf(rb.y, cb.y), 0.f);
        float inter = ih * iw;
        float iou = inter / (areaR + areaC - inter + 1e-8f);
        if (iou > NMS_THR) bits |= (1ULL << jj);
    }
    g_mask[((size_t)b * PRE_NMS + r) * NWORDS + blockIdx.x] = bits;
}

// one warp per batch: exact sequential greedy NMS over the bitmask + output write
__global__ void nms_serial_kernel(float* __restrict__ out) {
    int b = blockIdx.x;
    int lane = threadIdx.x; // 32 threads
    const unsigned long long* M = g_mask + (size_t)b * PRE_NMS * NWORDS;
    unsigned long long rem0 = 0, rem1 = 0, rem2 = 0;
    __shared__ int list[PROP];
    int kc = 0;
    int w0 = lane, w1 = lane + 32, w2 = lane + 64;
    unsigned long long n0 = (w0 < NWORDS) ? M[w0] : 0ULL;
    unsigned long long n1 = (w1 < NWORDS) ? M[w1] : 0ULL;
    unsigned long long n2 = (w2 < NWORDS) ? M[w2] : 0ULL;
    for (int i = 0; i < PRE_NMS; ++i) {
        unsigned long long c0 = n0, c1 = n1, c2 = n2;
        if (i + 1 < PRE_NMS) {
            const unsigned long long* row = M + (size_t)(i + 1) * NWORDS;
            n0 = (w0 < NWORDS) ? row[w0] : 0ULL;
            n1 = (w1 < NWORDS) ? row[w1] : 0ULL;
            n2 = (w2 < NWORDS) ? row[w2] : 0ULL;
        }
        int word = i >> 6, bit = i & 63;
        int src = word & 31, slot = word >> 5;
        unsigned long long mine = (slot == 0) ? rem0 : ((slot == 1) ? rem1 : rem2);
        unsigned long long v = __shfl_sync(0xffffffffu, mine, src);
        if (!((v >> bit) & 1ULL)) {
            if (lane == 0 && kc < PROP) list[kc] = i;
            kc++;
            rem0 |= c0; rem1 |= c1; rem2 |= c2;
            if (kc >= PROP) break;
        }
    }
    __syncwarp();
    const float4* bx = g_boxes + b * PRE_NMS;
    float4* o = (float4*)(out + (size_t)b * PROP * 4);
    for (int r = lane; r < PROP; r += 32) {
        float4 v = make_float4(0.f, 0.f, 0.f, 0.f);
        if (r < kc) v = bx[list[r]];
        o[r] = v;
    }
}

// ---------------- launch ----------------
extern "C" void kernel_launch(void* const* d_in, const int* in_sizes, int n_in,
                              void* d_out, int out_size) {
    (void)in_sizes; (void)n_in; (void)out_size;
    const float2* cls = (const float2*)d_in[0];     // (B,N,2)
    const float* rpn_bbox = (const float*)d_in[1];  // (B,N,4)
    const float* anchors = (const float*)d_in[2];   // (B,N,4)
    float* out = (float*)d_out;                     // (B,1000,4)

    cudaFuncSetAttribute(sort_kernel, cudaFuncAttributeMaxDynamicSharedMemorySize,
                         CAP * sizeof(unsigned long long));

    zero_kernel<<<(BATCH * NBINS + 1023) / 1024, 1024>>>();
    hist_kernel<<<256, 512>>>(cls);
    cutbin_kernel<<<BATCH, 1024>>>();
    {
        long long total = (long long)BATCH * NANCH;
        int blocks = (int)((total + 511) / 512);
        compact_kernel<<<blocks, 512>>>(cls);
    }
    sort_kernel<<<BATCH, 1024, CAP * sizeof(unsigned long long)>>>();
    boxes_kernel<<<(BATCH * PRE_NMS + 255) / 256, 256>>>(rpn_bbox, anchors);
    {
        dim3 grid(NWORDS, (PRE_NMS + 63) / 64, BATCH);
        mask_kernel<<<grid, 64>>>();
    }
    nms_serial_kernel<<<BATCH, 32>>>(out);
}